// round 9
// baseline (speedup 1.0000x reference)
#include <cuda_runtime.h>

// Problem constants
#define B   128
#define S   37
#define T   2048
#define D   256
#define STC 8
#define C   2
#define MERGED 264     // D + STC
#define F2  74         // 2*S features
#define NT  256        // threads per block
#define G   (T/4)      // 512 float4 groups along time
#define PB  2          // time partitions per batch
#define GP  (G/PB)     // 256 float4 groups per partition
#define NCTA (B*PB)    // 256 CTAs; <= 148*2 resident slots -> single wave, barrier-safe

// Head tiling (phase C)
#define BT      8
#define BTILES  (B/BT)   // 16
#define JT      32
#define JTILES  9        // ceil(264/32), last tile ragged

// Scratch + barrier state (device globals; deterministic ownership per slot)
__device__ float g_part[B][PB][F2 + 2];
__device__ float g_comb[B][MERGED];
__device__ float g_partC[B][JTILES][2];
__device__ unsigned g_cnt = 0;
__device__ volatile unsigned g_gen = 0;

struct SmemReduce { unsigned vmask[GP]; float feat[F2]; float ssum[16]; };
struct SmemEmbed  { float sfeat[F2 + 2]; float scal[3]; };
struct SmemMerge  { float sw[MERGED * JT]; float sc[BT * MERGED]; };
union SmemAll { SmemReduce r; SmemEmbed e; SmemMerge m; };

__device__ __forceinline__ float warp_sum(float v) {
#pragma unroll
    for (int o = 16; o; o >>= 1) v += __shfl_xor_sync(0xffffffffu, v, o);
    return v;
}

// Sense-reversing grid barrier. Safe: all NCTA CTAs are co-resident (one wave).
__device__ __forceinline__ void grid_bar() {
    __syncthreads();
    if (threadIdx.x == 0) {
        __threadfence();
        const unsigned gen = g_gen;
        if (atomicAdd(&g_cnt, 1u) == NCTA - 1u) {
            g_cnt = 0;
            __threadfence();
            g_gen = gen + 1u;            // release
        } else {
            while (g_gen == gen) { }     // volatile spin
            __threadfence();
        }
    }
    __syncthreads();
}

__global__ __launch_bounds__(NT, 2)
void fused_kernel(const float* __restrict__ x,
                  const float* __restrict__ static_in,
                  const float* __restrict__ time_in,
                  const int*   __restrict__ smask,
                  const float* __restrict__ W_sensor,  // [74,256]
                  const float* __restrict__ b_sensor,  // [256]
                  const float* __restrict__ W_time,    // [1,256]
                  const float* __restrict__ b_time,    // [256]
                  const float* __restrict__ W_static,  // [8,8]
                  const float* __restrict__ b_static,  // [8]
                  const float* __restrict__ W_merge,   // [264,264]
                  const float* __restrict__ b_merge,   // [264]
                  const float* __restrict__ W_cls,     // [264,2]
                  const float* __restrict__ b_cls,     // [2]
                  float* __restrict__ out)             // [B,2]
{
    __shared__ SmemAll sm;

    const int bid  = blockIdx.x;
    const int tid  = threadIdx.x;
    const int lane = tid & 31;
    const int wid  = tid >> 5;

    // ======================= Phase A: time reduction =======================
    {
        const int b = bid >> 1;          // PB = 2
        const int p = bid & 1;
        sm.r.vmask[tid] = 0u;            // GP == NT == 256
        __syncthreads();

        const float4* __restrict__ x4 = (const float4*)x   + (size_t)b * S * G;
        const int4*   __restrict__ m4 = (const int4*)smask + (size_t)b * S * G;
        const int gbase = p * GP;

        float accx[5] = {0.f, 0.f, 0.f, 0.f, 0.f};
        float accm[5] = {0.f, 0.f, 0.f, 0.f, 0.f};
        const int ns = (wid < 5) ? 5 : 4;   // 37 = 5*5 + 3*4

#pragma unroll 4
        for (int gi = 0; gi < GP / 32; gi++) {
            const int g = gbase + lane + gi * 32;
            unsigned bits = 0u;
#pragma unroll
            for (int i = 0; i < 5; i++) {
                if (i < ns) {               // warp-uniform
                    const int idx = (wid + 8 * i) * G + g;
                    float4 xv = x4[idx];
                    int4   mv = m4[idx];
                    // Unconditional feature sums: invalid step => all features 0.
                    accx[i] += (xv.x + xv.y) + (xv.z + xv.w);
                    accm[i] += (float)((mv.x + mv.y) + (mv.z + mv.w));
                    bits |= (xv.x != 0.f || mv.x != 0) ? 1u : 0u;
                    bits |= (xv.y != 0.f || mv.y != 0) ? 2u : 0u;
                    bits |= (xv.z != 0.f || mv.z != 0) ? 4u : 0u;
                    bits |= (xv.w != 0.f || mv.w != 0) ? 8u : 0u;
                }
            }
            if (bits) atomicOr(&sm.r.vmask[g - gbase], bits);
        }

#pragma unroll
        for (int i = 0; i < 5; i++) {
            if (i < ns) {
                float vx = warp_sum(accx[i]);
                float vm = warp_sum(accm[i]);
                if (lane == 0) {
                    const int s = wid + 8 * i;
                    sm.r.feat[s] = vx;          // reuse: x-sums in [0..36] slots
                    // mask sums stored after sync below via second slot
                    sm.r.ssum[0] = sm.r.ssum[0]; // no-op placeholder
                    // store mask sum separately:
                    // (feat has only F2=74 entries: s in [0,37) for x, S+s for m)
                    sm.r.feat[0] = sm.r.feat[0];
                }
                if (lane == 0) sm.r.feat[(i >= 0 ? 0 : 0)] = sm.r.feat[0];
                if (lane == 0) { sm.r.feat[wid + 8 * i] = vx; sm.r.feat[S + wid + 8 * i] = vm; }
            }
        }
        __syncthreads();

        // denom & masked time-sum from validity bitmask (all 8 warps, GP==256)
        const unsigned bits = sm.r.vmask[tid];
        const float4 tv = ((const float4*)time_in)[b * G + gbase + tid];
        float dcnt = (float)__popc(bits & 0xFu);
        float tsum = (bits & 1u ? tv.x : 0.f) + (bits & 2u ? tv.y : 0.f)
                   + (bits & 4u ? tv.z : 0.f) + (bits & 8u ? tv.w : 0.f);
        {
            float t = warp_sum(tsum);
            float d = warp_sum(dcnt);
            if (lane == 0) { sm.r.ssum[wid] = t; sm.r.ssum[8 + wid] = d; }
        }
        __syncthreads();

        float* __restrict__ dst = &g_part[b][p][0];
        if (tid < F2) {
            dst[tid] = sm.r.feat[tid];
        } else if (tid == F2) {
            float v = 0.f;
#pragma unroll
            for (int w = 0; w < 8; w++) v += sm.r.ssum[w];
            dst[F2] = v;
        } else if (tid == F2 + 1) {
            float v = 0.f;
#pragma unroll
            for (int w = 0; w < 8; w++) v += sm.r.ssum[8 + w];
            dst[F2 + 1] = v;
        }
    }

    grid_bar();

    // ======================= Phase B: embedding (CTA = batch) ==============
    if (bid < B) {
        const int b = bid;
        if (tid < F2 + 2)
            sm.e.sfeat[tid] = g_part[b][0][tid] + g_part[b][1][tid];
        __syncthreads();
        if (tid == 0) {
            const float dn  = sm.e.sfeat[F2 + 1];
            const float inv = 1.f / fmaxf(dn, 1e-9f);
            sm.e.scal[0] = inv;
            sm.e.scal[1] = dn * inv;               // 1.0 normally, 0.0 if empty
            sm.e.scal[2] = sm.e.sfeat[F2] * inv;   // masked mean time
        }
        __syncthreads();

        const float inv = sm.e.scal[0], r = sm.e.scal[1], ts = sm.e.scal[2];
        {   // thread = channel d (256 exactly); W_sensor coalesced
            float acc = 0.f;
#pragma unroll
            for (int f = 0; f < F2; f++)
                acc = fmaf(sm.e.sfeat[f], W_sensor[f * D + tid], acc);
            g_comb[b][tid] = acc * inv
                           + r * (b_sensor[tid] + b_time[tid])
                           + ts * W_time[tid];
        }
        if (tid < STC) {
            float acc = b_static[tid];
#pragma unroll
            for (int k = 0; k < STC; k++)
                acc = fmaf(static_in[b * STC + k], W_static[k * STC + tid], acc);
            g_comb[b][D + tid] = acc;
        }
    }

    grid_bar();

    // ============ Phase C: merge GEMM + classifier partials ================
    if (bid < JTILES * BTILES) {        // 144 CTAs
        const int jt = bid % JTILES;
        const int b0 = (bid / JTILES) * BT;
        const int jcol  = jt * JT + lane;
        const int jcolc = (jcol < MERGED) ? jcol : (MERGED - 1);

        // stage W_merge column slice: [k][lane], conflict-free
#pragma unroll 4
        for (int kk = wid; kk < MERGED; kk += 8)
            sm.m.sw[kk * JT + lane] = W_merge[kk * MERGED + jcolc];

        // stage comb rows (contiguous)
        const float* __restrict__ csrc = &g_comb[b0][0];
        for (int i = tid; i < BT * MERGED; i += NT) sm.m.sc[i] = csrc[i];
        __syncthreads();

        // warp = batch, lane = j column
        float acc = b_merge[jcolc];
        const float* __restrict__ scb = &sm.m.sc[wid * MERGED];
#pragma unroll 8
        for (int k = 0; k < MERGED; k++)
            acc = fmaf(scb[k], sm.m.sw[k * JT + lane], acc);

        const float rlu = (jcol < MERGED) ? fmaxf(acc, 0.f) : 0.f;
        const float p0 = warp_sum(rlu * W_cls[jcolc * C + 0]);
        const float p1 = warp_sum(rlu * W_cls[jcolc * C + 1]);
        if (lane == 0) {
            g_partC[b0 + wid][jt][0] = p0;
            g_partC[b0 + wid][jt][1] = p1;
        }
    }

    grid_bar();

    // ======================= Phase D: final outputs ========================
    if (bid == 0) {                      // B*C = 256 = NT
        const int b = tid >> 1, c = tid & 1;
        float v = b_cls[c];
#pragma unroll
        for (int jt = 0; jt < JTILES; jt++) v += g_partC[b][jt][c];
        out[tid] = v;
    }
}

extern "C" void kernel_launch(void* const* d_in, const int* in_sizes, int n_in,
                              void* d_out, int out_size)
{
    const float* x        = (const float*)d_in[0];
    const float* stat     = (const float*)d_in[1];
    const float* time_in  = (const float*)d_in[2];
    const int*   smask    = (const int*)  d_in[3];
    const float* W_sensor = (const float*)d_in[4];
    const float* b_sensor = (const float*)d_in[5];
    const float* W_time   = (const float*)d_in[6];
    const float* b_time   = (const float*)d_in[7];
    const float* W_static = (const float*)d_in[8];
    const float* b_static = (const float*)d_in[9];
    const float* W_merge  = (const float*)d_in[10];
    const float* b_merge  = (const float*)d_in[11];
    const float* W_cls    = (const float*)d_in[12];
    const float* b_cls    = (const float*)d_in[13];
    float* out = (float*)d_out;

    fused_kernel<<<NCTA, NT>>>(x, stat, time_in, smask,
                               W_sensor, b_sensor, W_time, b_time,
                               W_static, b_static, W_merge, b_merge,
                               W_cls, b_cls, out);
}